// round 13
// baseline (speedup 1.0000x reference)
#include <cuda_runtime.h>
#include <cstdint>

// Problem shape (fixed by dataset): D=1024, P=256, R=64, K=1024
#define D_DIRS 1024
#define P_PTS  256
#define R_RANK 64
#define K_SUB  1024

#define PREFETCH_BLOCKS 16
#define TMA_CHUNK_BYTES 16384

// Scratch (allocation-free rule: __device__ globals; fully rewritten each replay)
__device__ float g_asumT[R_RANK * D_DIRS];   // TRANSPOSED atten sums [r][d], 256 KB
__device__ float g_bsum[D_DIRS * R_RANK];    // radiation sums [d][r], 256 KB
__device__ float g_sink[PREFETCH_BLOCKS];

// ---------------- mbarrier / bulk-copy helpers ----------------
__device__ __forceinline__ uint32_t smem_u32(const void* p)
{
    uint32_t a;
    asm("{ .reg .u64 tmp; cvta.to.shared.u64 tmp, %1; cvt.u32.u64 %0, tmp; }"
        : "=r"(a) : "l"(p));
    return a;
}
__device__ __forceinline__ void mbar_init(uint32_t mbar, uint32_t count)
{
    asm volatile("mbarrier.init.shared.b64 [%0], %1;" :: "r"(mbar), "r"(count) : "memory");
}
__device__ __forceinline__ void mbar_expect_tx(uint32_t mbar, uint32_t bytes)
{
    asm volatile("mbarrier.arrive.expect_tx.shared.b64 _, [%0], %1;"
                 :: "r"(mbar), "r"(bytes) : "memory");
}
__device__ __forceinline__ void bulk_g2s(uint32_t dst_smem, const void* src_gmem,
                                         uint32_t bytes, uint32_t mbar)
{
    asm volatile(
        "cp.async.bulk.shared::cluster.global.mbarrier::complete_tx::bytes "
        "[%0], [%1], %2, [%3];"
        :: "r"(dst_smem), "l"(src_gmem), "r"(bytes), "r"(mbar) : "memory");
}
__device__ __forceinline__ void mbar_wait(uint32_t mbar, uint32_t phase)
{
    asm volatile(
        "{\n\t.reg .pred P;\n\t"
        "WAIT_%=:\n\t"
        "mbarrier.try_wait.parity.shared::cta.b64 P, [%0], %1;\n\t"
        "@!P bra WAIT_%=;\n\t"
        "}"
        :: "r"(mbar), "r"(phase) : "memory");
}

// ---------------------------------------------------------------------------
// Kernel 1: reduce over P via TMA bulk-copy pipeline (proven 24.2us @ 72%).
// atten blocks store their 64-float result TRANSPOSED into g_asumT (64
// scattered 4B stores per block); rad blocks store row-major into g_bsum.
// Prefetch blocks warm L2 with F; prefetch block 0 also zeroes `out` for the
// tail's atomic accumulation (ordered by the PDL grid dependency).
// ---------------------------------------------------------------------------
__global__ __launch_bounds__(256) void reduce_p_kernel(
    const float* __restrict__ atten, const float* __restrict__ rad,
    const float* __restrict__ F, float* __restrict__ out)
{
    __shared__ __align__(1024) float4 buf[2][1024];   // 2 x 16 KB
    __shared__ uint64_t mb[2];

    const int b = blockIdx.x;
    const int t = threadIdx.x;

    if (b >= 2 * D_DIRS) {
        const int pb = b - 2 * D_DIRS;
        if (pb == 0) {
            // zero out[1024] = 256 float4
            reinterpret_cast<float4*>(out)[t] = make_float4(0.f, 0.f, 0.f, 0.f);
        }
        const float4* __restrict__ f4 =
            reinterpret_cast<const float4*>(F) + (size_t)pb * 1024;
        float4 acc = make_float4(0.f, 0.f, 0.f, 0.f);
        #pragma unroll
        for (int i = 0; i < 4; i++) {
            float4 v = f4[i * 256 + t];
            acc.x += v.x; acc.y += v.y; acc.z += v.z; acc.w += v.w;
        }
        if (t == 0) g_sink[pb] = acc.x + acc.y + acc.z + acc.w;
        cudaTriggerProgrammaticLaunchCompletion();
        return;
    }

    const bool is_b = (b >= D_DIRS);
    const int d = b & (D_DIRS - 1);
    const float* __restrict__ src = is_b ? rad : atten;
    const char* slab = reinterpret_cast<const char*>(src)
                       + (size_t)d * (P_PTS * R_RANK * sizeof(float));

    const uint32_t mb0  = smem_u32(&mb[0]);
    const uint32_t mb1  = smem_u32(&mb[1]);
    const uint32_t buf0 = smem_u32(&buf[0][0]);
    const uint32_t buf1 = smem_u32(&buf[1][0]);

    if (t == 0) {
        mbar_init(mb0, 1);
        mbar_init(mb1, 1);
    }
    __syncthreads();

    if (t == 0) {
        mbar_expect_tx(mb0, TMA_CHUNK_BYTES);
        bulk_g2s(buf0, slab + 0 * TMA_CHUNK_BYTES, TMA_CHUNK_BYTES, mb0);
        mbar_expect_tx(mb1, TMA_CHUNK_BYTES);
        bulk_g2s(buf1, slab + 1 * TMA_CHUNK_BYTES, TMA_CHUNK_BYTES, mb1);
    }

    float4 acc = make_float4(0.f, 0.f, 0.f, 0.f);

    mbar_wait(mb0, 0);
    #pragma unroll
    for (int q = 0; q < 4; q++) {
        float4 v = buf[0][q * 256 + t];
        acc.x += v.x; acc.y += v.y; acc.z += v.z; acc.w += v.w;
    }
    __syncthreads();
    if (t == 0) {
        mbar_expect_tx(mb0, TMA_CHUNK_BYTES);
        bulk_g2s(buf0, slab + 2 * TMA_CHUNK_BYTES, TMA_CHUNK_BYTES, mb0);
    }

    mbar_wait(mb1, 0);
    #pragma unroll
    for (int q = 0; q < 4; q++) {
        float4 v = buf[1][q * 256 + t];
        acc.x += v.x; acc.y += v.y; acc.z += v.z; acc.w += v.w;
    }
    __syncthreads();
    if (t == 0) {
        mbar_expect_tx(mb1, TMA_CHUNK_BYTES);
        bulk_g2s(buf1, slab + 3 * TMA_CHUNK_BYTES, TMA_CHUNK_BYTES, mb1);
    }

    mbar_wait(mb0, 1);
    #pragma unroll
    for (int q = 0; q < 4; q++) {
        float4 v = buf[0][q * 256 + t];
        acc.x += v.x; acc.y += v.y; acc.z += v.z; acc.w += v.w;
    }

    mbar_wait(mb1, 1);
    #pragma unroll
    for (int q = 0; q < 4; q++) {
        float4 v = buf[1][q * 256 + t];
        acc.x += v.x; acc.y += v.y; acc.z += v.z; acc.w += v.w;
    }

    // tree reduce (thread t writes slot t; only thread t's slot read by reducers)
    float4* s = &buf[0][0];
    s[t] = acc;
    __syncthreads();

    if (t < 16) {
        float4 sum = s[t];
        #pragma unroll
        for (int j = 1; j < 16; j++) {
            float4 v = s[j * 16 + t];
            sum.x += v.x; sum.y += v.y; sum.z += v.z; sum.w += v.w;
        }
        if (is_b) {
            reinterpret_cast<float4*>(g_bsum + d * R_RANK)[t] = sum;
        } else {
            // transposed scatter: r = 4t..4t+3
            g_asumT[(4 * t + 0) * D_DIRS + d] = sum.x;
            g_asumT[(4 * t + 1) * D_DIRS + d] = sum.y;
            g_asumT[(4 * t + 2) * D_DIRS + d] = sum.z;
            g_asumT[(4 * t + 3) * D_DIRS + d] = sum.w;
        }
    }
    cudaTriggerProgrammaticLaunchCompletion();
}

// ---------------------------------------------------------------------------
// Kernel 2 (single PDL tail): 32 blocks x 256 threads; block owns r1 pair
// (2b, 2b+1). Computes the two final M rows from g_asumT (coalesced) and
// g_bsum (16 double-buffered 16 KB chunks, L2-hot), then the quadform
// contribution for ALL 1024 k's with one spread atomicAdd per k (depth 32).
// ---------------------------------------------------------------------------
__global__ __launch_bounds__(256) void tail_kernel(
    const float* __restrict__ F, float* __restrict__ out)
{
    __shared__ __align__(16) float aA[D_DIRS];     // 4 KB  asumT row r1a
    __shared__ __align__(16) float aB[D_DIRS];     // 4 KB  asumT row r1b
    __shared__ __align__(16) float sB[64 * R_RANK];// 16 KB bsum chunk
    __shared__ float redA[256], redB[256];
    __shared__ float MrowA[R_RANK], MrowB[R_RANK];

    const int t   = threadIdx.x;
    const int r1a = 2 * blockIdx.x;
    const int r1b = r1a + 1;

    cudaGridDependencySynchronize();   // stream fully complete (incl. out=0)

    reinterpret_cast<float4*>(aA)[t] =
        reinterpret_cast<const float4*>(g_asumT + (size_t)r1a * D_DIRS)[t];
    reinterpret_cast<float4*>(aB)[t] =
        reinterpret_cast<const float4*>(g_asumT + (size_t)r1b * D_DIRS)[t];

    const int r2 = t & 63;
    const int g  = t >> 6;   // d-quarter within chunk

    // register-double-buffered bsum chunks
    const float4* __restrict__ b4 = reinterpret_cast<const float4*>(g_bsum);
    float4 v[4];
    #pragma unroll
    for (int i = 0; i < 4; i++) v[i] = b4[i * 256 + t];

    float accA = 0.f, accB = 0.f;
    for (int c = 0; c < 16; c++) {
        __syncthreads();   // previous chunk consumed (and aA/aB staged, c==0)
        #pragma unroll
        for (int i = 0; i < 4; i++)
            reinterpret_cast<float4*>(sB)[i * 256 + t] = v[i];
        __syncthreads();

        if (c < 15) {
            const float4* __restrict__ nb = b4 + (size_t)(c + 1) * 1024;
            #pragma unroll
            for (int i = 0; i < 4; i++) v[i] = nb[i * 256 + t];
        }

        const int dbase = c * 64 + g * 16;
        #pragma unroll
        for (int i = 0; i < 16; i++) {
            const float bv = sB[(g * 16 + i) * R_RANK + r2];
            accA += aA[dbase + i] * bv;
            accB += aB[dbase + i] * bv;
        }
    }

    redA[t] = accA;
    redB[t] = accB;
    __syncthreads();
    if (t < 64)
        MrowA[t] = redA[t] + redA[64 + t] + redA[128 + t] + redA[192 + t];
    else if (t < 128)
        MrowB[t - 64] = redB[t - 64] + redB[t] + redB[64 + t] + redB[128 + t];
    __syncthreads();

    // ---- quadform contribution for all k: one spread atomic per k ----
    const float inv = 1.0f / (float)D_DIRS;
    #pragma unroll
    for (int j = 0; j < 4; j++) {
        const int k = j * 256 + t;
        const float4* __restrict__ f4 =
            reinterpret_cast<const float4*>(F) + (size_t)k * 16;

        float dotA = 0.f, dotB = 0.f;
        #pragma unroll
        for (int i = 0; i < 16; i++) {
            const float4 fv = f4[i];   // L2-hot from stream prefetch
            dotA += fv.x * MrowA[4*i+0] + fv.y * MrowA[4*i+1]
                  + fv.z * MrowA[4*i+2] + fv.w * MrowA[4*i+3];
            dotB += fv.x * MrowB[4*i+0] + fv.y * MrowB[4*i+1]
                  + fv.z * MrowB[4*i+2] + fv.w * MrowB[4*i+3];
        }
        const float fr1a = F[(size_t)k * R_RANK + r1a];   // L1 hit
        const float fr1b = F[(size_t)k * R_RANK + r1b];
        atomicAdd(&out[k], (dotA * fr1a + dotB * fr1b) * inv);
    }
}

extern "C" void kernel_launch(void* const* d_in, const int* in_sizes, int n_in,
                              void* d_out, int out_size)
{
    const float* atten = (const float*)d_in[0];   // [D,P,R] fp32
    const float* rad   = (const float*)d_in[1];   // [D,P,R] fp32
    const float* F     = (const float*)d_in[2];   // [K,R]   fp32
    float* out = (float*)d_out;                   // [K]     fp32

    (void)in_sizes; (void)n_in; (void)out_size;

    reduce_p_kernel<<<2 * D_DIRS + PREFETCH_BLOCKS, 256>>>(atten, rad, F, out);

    cudaLaunchAttribute attr[1];
    attr[0].id = cudaLaunchAttributeProgrammaticStreamSerialization;
    attr[0].val.programmaticStreamSerializationAllowed = 1;

    cudaLaunchConfig_t cfg = {};
    cfg.blockDim = dim3(256, 1, 1);
    cfg.attrs = attr;
    cfg.numAttrs = 1;
    cfg.stream = 0;

    cfg.gridDim = dim3(R_RANK / 2, 1, 1);   // 32 blocks
    cudaLaunchKernelEx(&cfg, tail_kernel, F, out);
}

// round 14
// speedup vs baseline: 1.3655x; 1.3655x over previous
#include <cuda_runtime.h>
#include <cstdint>

// Problem shape (fixed by dataset): D=1024, P=256, R=64, K=1024
#define D_DIRS 1024
#define P_PTS  256
#define R_RANK 64
#define K_SUB  1024

#define PREFETCH_BLOCKS 16
#define TMA_CHUNK_BYTES 16384

#define NCHUNK 8
#define CHUNK_D (D_DIRS / NCHUNK)   // 128 directions per chunk

// Scratch (allocation-free rule: __device__ globals; fully rewritten each
// replay — no zeroing, no atomics anywhere)
__device__ float g_asum[D_DIRS * R_RANK];
__device__ float g_bsum[D_DIRS * R_RANK];
__device__ float g_part[NCHUNK * R_RANK * R_RANK];   // 128 KB
__device__ float g_sink[PREFETCH_BLOCKS];

// ---------------- mbarrier / bulk-copy helpers ----------------
__device__ __forceinline__ uint32_t smem_u32(const void* p)
{
    uint32_t a;
    asm("{ .reg .u64 tmp; cvta.to.shared.u64 tmp, %1; cvt.u32.u64 %0, tmp; }"
        : "=r"(a) : "l"(p));
    return a;
}
__device__ __forceinline__ void mbar_init(uint32_t mbar, uint32_t count)
{
    asm volatile("mbarrier.init.shared.b64 [%0], %1;" :: "r"(mbar), "r"(count) : "memory");
}
__device__ __forceinline__ void mbar_expect_tx(uint32_t mbar, uint32_t bytes)
{
    asm volatile("mbarrier.arrive.expect_tx.shared.b64 _, [%0], %1;"
                 :: "r"(mbar), "r"(bytes) : "memory");
}
__device__ __forceinline__ void bulk_g2s(uint32_t dst_smem, const void* src_gmem,
                                         uint32_t bytes, uint32_t mbar)
{
    asm volatile(
        "cp.async.bulk.shared::cluster.global.mbarrier::complete_tx::bytes "
        "[%0], [%1], %2, [%3];"
        :: "r"(dst_smem), "l"(src_gmem), "r"(bytes), "r"(mbar) : "memory");
}
__device__ __forceinline__ void mbar_wait(uint32_t mbar, uint32_t phase)
{
    asm volatile(
        "{\n\t.reg .pred P;\n\t"
        "WAIT_%=:\n\t"
        "mbarrier.try_wait.parity.shared::cta.b64 P, [%0], %1;\n\t"
        "@!P bra WAIT_%=;\n\t"
        "}"
        :: "r"(mbar), "r"(phase) : "memory");
}

// ---------------------------------------------------------------------------
// Kernel 1: reduce over P via TMA bulk-copy pipeline (proven 24.2us @ 72%).
// One block per (tensor, d): 4 x 16 KB cp.async.bulk bursts, double-buffered.
// 16 extra blocks prefetch F (256 KB) into L2 for the tail.
// ---------------------------------------------------------------------------
__global__ __launch_bounds__(256) void reduce_p_kernel(
    const float* __restrict__ atten, const float* __restrict__ rad,
    const float* __restrict__ F)
{
    __shared__ __align__(1024) float4 buf[2][1024];   // 2 x 16 KB
    __shared__ uint64_t mb[2];

    const int b = blockIdx.x;
    const int t = threadIdx.x;

    if (b >= 2 * D_DIRS) {
        const int pb = b - 2 * D_DIRS;
        const float4* __restrict__ f4 =
            reinterpret_cast<const float4*>(F) + (size_t)pb * 1024;
        float4 acc = make_float4(0.f, 0.f, 0.f, 0.f);
        #pragma unroll
        for (int i = 0; i < 4; i++) {
            float4 v = f4[i * 256 + t];
            acc.x += v.x; acc.y += v.y; acc.z += v.z; acc.w += v.w;
        }
        if (t == 0) g_sink[pb] = acc.x + acc.y + acc.z + acc.w;
        cudaTriggerProgrammaticLaunchCompletion();
        return;
    }

    const bool is_b = (b >= D_DIRS);
    const int d = b & (D_DIRS - 1);
    const float* __restrict__ src = is_b ? rad : atten;
    float* __restrict__ dst = is_b ? g_bsum : g_asum;
    const char* slab = reinterpret_cast<const char*>(src)
                       + (size_t)d * (P_PTS * R_RANK * sizeof(float));

    const uint32_t mb0  = smem_u32(&mb[0]);
    const uint32_t mb1  = smem_u32(&mb[1]);
    const uint32_t buf0 = smem_u32(&buf[0][0]);
    const uint32_t buf1 = smem_u32(&buf[1][0]);

    if (t == 0) {
        mbar_init(mb0, 1);
        mbar_init(mb1, 1);
    }
    __syncthreads();

    if (t == 0) {
        mbar_expect_tx(mb0, TMA_CHUNK_BYTES);
        bulk_g2s(buf0, slab + 0 * TMA_CHUNK_BYTES, TMA_CHUNK_BYTES, mb0);
        mbar_expect_tx(mb1, TMA_CHUNK_BYTES);
        bulk_g2s(buf1, slab + 1 * TMA_CHUNK_BYTES, TMA_CHUNK_BYTES, mb1);
    }

    float4 acc = make_float4(0.f, 0.f, 0.f, 0.f);

    mbar_wait(mb0, 0);
    #pragma unroll
    for (int q = 0; q < 4; q++) {
        float4 v = buf[0][q * 256 + t];
        acc.x += v.x; acc.y += v.y; acc.z += v.z; acc.w += v.w;
    }
    __syncthreads();
    if (t == 0) {
        mbar_expect_tx(mb0, TMA_CHUNK_BYTES);
        bulk_g2s(buf0, slab + 2 * TMA_CHUNK_BYTES, TMA_CHUNK_BYTES, mb0);
    }

    mbar_wait(mb1, 0);
    #pragma unroll
    for (int q = 0; q < 4; q++) {
        float4 v = buf[1][q * 256 + t];
        acc.x += v.x; acc.y += v.y; acc.z += v.z; acc.w += v.w;
    }
    __syncthreads();
    if (t == 0) {
        mbar_expect_tx(mb1, TMA_CHUNK_BYTES);
        bulk_g2s(buf1, slab + 3 * TMA_CHUNK_BYTES, TMA_CHUNK_BYTES, mb1);
    }

    mbar_wait(mb0, 1);
    #pragma unroll
    for (int q = 0; q < 4; q++) {
        float4 v = buf[0][q * 256 + t];
        acc.x += v.x; acc.y += v.y; acc.z += v.z; acc.w += v.w;
    }

    mbar_wait(mb1, 1);
    #pragma unroll
    for (int q = 0; q < 4; q++) {
        float4 v = buf[1][q * 256 + t];
        acc.x += v.x; acc.y += v.y; acc.z += v.z; acc.w += v.w;
    }

    // tree reduce (slot t written by thread t, read only by thread t before)
    float4* s = &buf[0][0];
    s[t] = acc;
    __syncthreads();

    if (t < 16) {
        float4 sum = s[t];
        #pragma unroll
        for (int j = 1; j < 16; j++) {
            float4 v = s[j * 16 + t];
            sum.x += v.x; sum.y += v.y; sum.z += v.z; sum.w += v.w;
        }
        reinterpret_cast<float4*>(dst + d * R_RANK)[t] = sum;
    }
    cudaTriggerProgrammaticLaunchCompletion();
}

// ---------------------------------------------------------------------------
// Kernel 2 (PDL): partial M. 32 blocks = (chunk c = b>>2 of 128 d's,
// r1-quarter q = b&3). Stage both 32 KB chunk slices in smem (8 batched
// float4 loads/thread per tensor), 512 FMA/thread, plain float4 store.
// ---------------------------------------------------------------------------
__global__ __launch_bounds__(256) void partial_m_kernel()
{
    __shared__ __align__(16) float sA[CHUNK_D * R_RANK];   // 32 KB
    __shared__ __align__(16) float sB[CHUNK_D * R_RANK];   // 32 KB

    const int t = threadIdx.x;
    const int c = blockIdx.x >> 2;
    const int q = blockIdx.x & 3;

    cudaGridDependencySynchronize();   // reduce_p's writes visible

    const float4* __restrict__ a4 =
        reinterpret_cast<const float4*>(g_asum) + (size_t)c * 2048;
    const float4* __restrict__ b4 =
        reinterpret_cast<const float4*>(g_bsum) + (size_t)c * 2048;
    #pragma unroll
    for (int i = 0; i < 8; i++) {
        reinterpret_cast<float4*>(sA)[i * 256 + t] = a4[i * 256 + t];
        reinterpret_cast<float4*>(sB)[i * 256 + t] = b4[i * 256 + t];
    }
    __syncthreads();

    const int r1  = q * 16 + (t >> 4);
    const int r2b = (t & 15) * 4;

    float4 m = make_float4(0.f, 0.f, 0.f, 0.f);
    #pragma unroll 8
    for (int dd = 0; dd < CHUNK_D; dd++) {
        const float a = sA[dd * R_RANK + r1];
        const float4 bv = *reinterpret_cast<const float4*>(sB + dd * R_RANK + r2b);
        m.x += a * bv.x; m.y += a * bv.y;
        m.z += a * bv.z; m.w += a * bv.w;
    }

    *reinterpret_cast<float4*>(g_part + (size_t)c * 4096 + r1 * R_RANK + r2b) = m;
    cudaTriggerProgrammaticLaunchCompletion();
}

// ---------------------------------------------------------------------------
// Kernel 3 (PDL): combine + quadform. 32 blocks x 256 threads, 32 k's each.
// F prestaged BEFORE the grid dependency (overlaps the predecessors).
// Combine: 8 partials x 4 batched float4 loads/thread (4 MB total L2 traffic,
// vs 16 MB in the round-12 version). Quadform: warp per k, 4 passes.
// ---------------------------------------------------------------------------
__global__ __launch_bounds__(256) void combine_quad_kernel(
    const float* __restrict__ F, float* __restrict__ out)
{
    __shared__ __align__(16) float Msh[R_RANK * R_RANK];   // 16 KB
    __shared__ __align__(16) float fsh[32 * R_RANK];       // 8 KB

    const int t = threadIdx.x;
    const int b = blockIdx.x;

    // prestage F rows for this block's 32 k's (2048 floats = 512 float4)
    {
        const float4* __restrict__ f4 =
            reinterpret_cast<const float4*>(F) + (size_t)b * 512;
        reinterpret_cast<float4*>(fsh)[t]       = f4[t];
        reinterpret_cast<float4*>(fsh)[256 + t] = f4[256 + t];
    }

    cudaGridDependencySynchronize();   // partial_m's writes visible

    const float4* __restrict__ p4 = reinterpret_cast<const float4*>(g_part);
    float4 acc[4];
    #pragma unroll
    for (int i = 0; i < 4; i++) acc[i] = make_float4(0.f, 0.f, 0.f, 0.f);

    #pragma unroll
    for (int p = 0; p < NCHUNK; p++) {
        #pragma unroll
        for (int i = 0; i < 4; i++) {
            const float4 v = p4[(size_t)p * 1024 + i * 256 + t];
            acc[i].x += v.x; acc[i].y += v.y;
            acc[i].z += v.z; acc[i].w += v.w;
        }
    }
    #pragma unroll
    for (int i = 0; i < 4; i++)
        reinterpret_cast<float4*>(Msh)[i * 256 + t] = acc[i];
    __syncthreads();

    const int w    = t >> 5;
    const int lane = t & 31;
    const float2* __restrict__ M2 = reinterpret_cast<const float2*>(Msh);

    #pragma unroll
    for (int pass = 0; pass < 4; pass++) {
        const int kl = w + pass * 8;              // 32 local k's
        const float* __restrict__ fk = fsh + kl * R_RANK;

        float2 a2 = make_float2(0.f, 0.f);
        #pragma unroll
        for (int r1 = 0; r1 < R_RANK; r1++) {
            const float fv = fk[r1];              // warp-uniform broadcast
            const float2 mv = M2[r1 * 32 + lane];
            a2.x += fv * mv.x;
            a2.y += fv * mv.y;
        }
        float val = a2.x * fk[2 * lane] + a2.y * fk[2 * lane + 1];

        #pragma unroll
        for (int off = 16; off > 0; off >>= 1)
            val += __shfl_xor_sync(0xffffffffu, val, off);

        if (lane == 0)
            out[b * 32 + kl] = val * (1.0f / (float)D_DIRS);
    }
}

extern "C" void kernel_launch(void* const* d_in, const int* in_sizes, int n_in,
                              void* d_out, int out_size)
{
    const float* atten = (const float*)d_in[0];   // [D,P,R] fp32
    const float* rad   = (const float*)d_in[1];   // [D,P,R] fp32
    const float* F     = (const float*)d_in[2];   // [K,R]   fp32
    float* out = (float*)d_out;                   // [K]     fp32

    (void)in_sizes; (void)n_in; (void)out_size;

    reduce_p_kernel<<<2 * D_DIRS + PREFETCH_BLOCKS, 256>>>(atten, rad, F);

    cudaLaunchAttribute attr[1];
    attr[0].id = cudaLaunchAttributeProgrammaticStreamSerialization;
    attr[0].val.programmaticStreamSerializationAllowed = 1;

    cudaLaunchConfig_t cfg = {};
    cfg.blockDim = dim3(256, 1, 1);
    cfg.attrs = attr;
    cfg.numAttrs = 1;
    cfg.stream = 0;

    cfg.gridDim = dim3(32, 1, 1);
    cudaLaunchKernelEx(&cfg, partial_m_kernel);

    cfg.gridDim = dim3(32, 1, 1);
    cudaLaunchKernelEx(&cfg, combine_quad_kernel, F, out);
}

// round 15
// speedup vs baseline: 1.4126x; 1.0346x over previous
#include <cuda_runtime.h>
#include <cstdint>

// Problem shape (fixed by dataset): D=1024, P=256, R=64, K=1024
#define D_DIRS 1024
#define P_PTS  256
#define R_RANK 64
#define K_SUB  1024

#define PREFETCH_BLOCKS 16
#define TMA_CHUNK_BYTES 16384

#define CLUSTER_SZ 8          // blocks per cluster (HW-portable max)
#define NCLUSTER   8          // clusters: each owns 8 r1 rows
#define TAIL_BLOCKS (CLUSTER_SZ * NCLUSTER)   // 64

// Scratch (allocation-free rule: __device__ globals; fully rewritten each replay)
__device__ float g_asum[D_DIRS * R_RANK];
__device__ float g_bsum[D_DIRS * R_RANK];
__device__ float g_partc[NCLUSTER * CLUSTER_SZ * 8 * R_RANK];  // 128 KB
__device__ float g_sink[PREFETCH_BLOCKS];

// ---------------- mbarrier / bulk-copy helpers ----------------
__device__ __forceinline__ uint32_t smem_u32(const void* p)
{
    uint32_t a;
    asm("{ .reg .u64 tmp; cvta.to.shared.u64 tmp, %1; cvt.u32.u64 %0, tmp; }"
        : "=r"(a) : "l"(p));
    return a;
}
__device__ __forceinline__ void mbar_init(uint32_t mbar, uint32_t count)
{
    asm volatile("mbarrier.init.shared.b64 [%0], %1;" :: "r"(mbar), "r"(count) : "memory");
}
__device__ __forceinline__ void mbar_expect_tx(uint32_t mbar, uint32_t bytes)
{
    asm volatile("mbarrier.arrive.expect_tx.shared.b64 _, [%0], %1;"
                 :: "r"(mbar), "r"(bytes) : "memory");
}
__device__ __forceinline__ void bulk_g2s(uint32_t dst_smem, const void* src_gmem,
                                         uint32_t bytes, uint32_t mbar)
{
    asm volatile(
        "cp.async.bulk.shared::cluster.global.mbarrier::complete_tx::bytes "
        "[%0], [%1], %2, [%3];"
        :: "r"(dst_smem), "l"(src_gmem), "r"(bytes), "r"(mbar) : "memory");
}
__device__ __forceinline__ void mbar_wait(uint32_t mbar, uint32_t phase)
{
    asm volatile(
        "{\n\t.reg .pred P;\n\t"
        "WAIT_%=:\n\t"
        "mbarrier.try_wait.parity.shared::cta.b64 P, [%0], %1;\n\t"
        "@!P bra WAIT_%=;\n\t"
        "}"
        :: "r"(mbar), "r"(phase) : "memory");
}

// ---------------------------------------------------------------------------
// Kernel 1: reduce over P via TMA bulk-copy pipeline (proven ~24.2us @ 72%).
// 16 extra blocks prefetch F into L2; prefetch block 0 also zeroes `out`
// (ordered before the tail's atomics by the PDL grid dependency).
// ---------------------------------------------------------------------------
__global__ __launch_bounds__(256) void reduce_p_kernel(
    const float* __restrict__ atten, const float* __restrict__ rad,
    const float* __restrict__ F, float* __restrict__ out)
{
    __shared__ __align__(1024) float4 buf[2][1024];   // 2 x 16 KB
    __shared__ uint64_t mb[2];

    const int b = blockIdx.x;
    const int t = threadIdx.x;

    if (b >= 2 * D_DIRS) {
        const int pb = b - 2 * D_DIRS;
        if (pb == 0)
            reinterpret_cast<float4*>(out)[t] = make_float4(0.f, 0.f, 0.f, 0.f);
        const float4* __restrict__ f4 =
            reinterpret_cast<const float4*>(F) + (size_t)pb * 1024;
        float4 acc = make_float4(0.f, 0.f, 0.f, 0.f);
        #pragma unroll
        for (int i = 0; i < 4; i++) {
            float4 v = f4[i * 256 + t];
            acc.x += v.x; acc.y += v.y; acc.z += v.z; acc.w += v.w;
        }
        if (t == 0) g_sink[pb] = acc.x + acc.y + acc.z + acc.w;
        cudaTriggerProgrammaticLaunchCompletion();
        return;
    }

    const bool is_b = (b >= D_DIRS);
    const int d = b & (D_DIRS - 1);
    const float* __restrict__ src = is_b ? rad : atten;
    float* __restrict__ dst = is_b ? g_bsum : g_asum;
    const char* slab = reinterpret_cast<const char*>(src)
                       + (size_t)d * (P_PTS * R_RANK * sizeof(float));

    const uint32_t mb0  = smem_u32(&mb[0]);
    const uint32_t mb1  = smem_u32(&mb[1]);
    const uint32_t buf0 = smem_u32(&buf[0][0]);
    const uint32_t buf1 = smem_u32(&buf[1][0]);

    if (t == 0) { mbar_init(mb0, 1); mbar_init(mb1, 1); }
    __syncthreads();

    if (t == 0) {
        mbar_expect_tx(mb0, TMA_CHUNK_BYTES);
        bulk_g2s(buf0, slab + 0 * TMA_CHUNK_BYTES, TMA_CHUNK_BYTES, mb0);
        mbar_expect_tx(mb1, TMA_CHUNK_BYTES);
        bulk_g2s(buf1, slab + 1 * TMA_CHUNK_BYTES, TMA_CHUNK_BYTES, mb1);
    }

    float4 acc = make_float4(0.f, 0.f, 0.f, 0.f);

    mbar_wait(mb0, 0);
    #pragma unroll
    for (int q = 0; q < 4; q++) {
        float4 v = buf[0][q * 256 + t];
        acc.x += v.x; acc.y += v.y; acc.z += v.z; acc.w += v.w;
    }
    __syncthreads();
    if (t == 0) {
        mbar_expect_tx(mb0, TMA_CHUNK_BYTES);
        bulk_g2s(buf0, slab + 2 * TMA_CHUNK_BYTES, TMA_CHUNK_BYTES, mb0);
    }

    mbar_wait(mb1, 0);
    #pragma unroll
    for (int q = 0; q < 4; q++) {
        float4 v = buf[1][q * 256 + t];
        acc.x += v.x; acc.y += v.y; acc.z += v.z; acc.w += v.w;
    }
    __syncthreads();
    if (t == 0) {
        mbar_expect_tx(mb1, TMA_CHUNK_BYTES);
        bulk_g2s(buf1, slab + 3 * TMA_CHUNK_BYTES, TMA_CHUNK_BYTES, mb1);
    }

    mbar_wait(mb0, 1);
    #pragma unroll
    for (int q = 0; q < 4; q++) {
        float4 v = buf[0][q * 256 + t];
        acc.x += v.x; acc.y += v.y; acc.z += v.z; acc.w += v.w;
    }

    mbar_wait(mb1, 1);
    #pragma unroll
    for (int q = 0; q < 4; q++) {
        float4 v = buf[1][q * 256 + t];
        acc.x += v.x; acc.y += v.y; acc.z += v.z; acc.w += v.w;
    }

    float4* s = &buf[0][0];
    s[t] = acc;
    __syncthreads();

    if (t < 16) {
        float4 sum = s[t];
        #pragma unroll
        for (int j = 1; j < 16; j++) {
            float4 v = s[j * 16 + t];
            sum.x += v.x; sum.y += v.y; sum.z += v.z; sum.w += v.w;
        }
        reinterpret_cast<float4*>(dst + d * R_RANK)[t] = sum;
    }
    cudaTriggerProgrammaticLaunchCompletion();
}

// ---------------------------------------------------------------------------
// Kernel 2 (single PDL tail, cluster-synced): 64 blocks = 8 clusters x 8.
// Cluster cid owns M rows r1 in [8cid, 8cid+8). Block cr computes those rows
// over d-chunk [128cr, +128) -> global partial -> cluster barrier -> each
// block sums its cluster's 8 partials -> quadform contribution of those 8
// rows for k-slice [128cr, +128), spread atomicAdd into out (depth 8).
// ---------------------------------------------------------------------------
__global__ __launch_bounds__(256) void tail_kernel(
    const float* __restrict__ F, float* __restrict__ out)
{
    __shared__ __align__(16) float sB[128 * R_RANK];   // 32 KB  bsum chunk
    __shared__ __align__(16) float sAc[128 * 8];       // 4 KB   asum columns
    __shared__ __align__(16) float Mc[8 * R_RANK];     // 2 KB   cluster M rows

    const int t   = threadIdx.x;
    const int cid = blockIdx.x / CLUSTER_SZ;   // cluster id -> r1 range
    const int cr  = blockIdx.x % CLUSTER_SZ;   // rank -> d chunk & k slice

    // ---- prestage F (independent of predecessors) into registers ----
    const int kl = t >> 1, half = t & 1;
    const int k  = cr * 128 + kl;
    const float4* __restrict__ fr =
        reinterpret_cast<const float4*>(F) + (size_t)k * 16;
    float4 f[8];
    #pragma unroll
    for (int j = 0; j < 8; j++) f[j] = fr[half * 8 + j];
    const float4 f8a = fr[2 * cid];        // f_k[8cid .. 8cid+3]
    const float4 f8b = fr[2 * cid + 1];    // f_k[8cid+4 .. 8cid+7]

    cudaGridDependencySynchronize();       // stream complete (incl. out = 0)

    // ================= Phase 1: partial M rows over 128 d's ================
    const int dbase = cr * 128;
    {
        const float4* __restrict__ b4 =
            reinterpret_cast<const float4*>(g_bsum) + (size_t)dbase * 16;
        #pragma unroll
        for (int i = 0; i < 8; i++)
            reinterpret_cast<float4*>(sB)[i * 256 + t] = b4[i * 256 + t];
        #pragma unroll
        for (int i = 0; i < 4; i++) {
            const int idx = i * 256 + t;
            const int dl = idx >> 3, rr = idx & 7;
            sAc[idx] = g_asum[(size_t)(dbase + dl) * R_RANK + 8 * cid + rr];
        }
    }
    __syncthreads();

    {
        const int r1l = t >> 5;          // warp-uniform
        const int r2p = t & 31;          // float2 of r2
        float2 acc = make_float2(0.f, 0.f);
        #pragma unroll 8
        for (int d = 0; d < 128; d++) {
            const float a = sAc[d * 8 + r1l];
            const float2 bv =
                reinterpret_cast<const float2*>(sB + d * R_RANK)[r2p];
            acc.x += a * bv.x;
            acc.y += a * bv.y;
        }
        reinterpret_cast<float2*>(
            g_partc + ((size_t)cid * CLUSTER_SZ + cr) * (8 * R_RANK))[t] = acc;
    }
    __threadfence();
    asm volatile("barrier.cluster.arrive.aligned;" ::: "memory");
    asm volatile("barrier.cluster.wait.aligned;" ::: "memory");

    // ================= Phase 2: combine cluster partials -> Mc =============
    {
        const float2* __restrict__ pp = reinterpret_cast<const float2*>(
            g_partc + (size_t)cid * CLUSTER_SZ * (8 * R_RANK));
        float2 s = make_float2(0.f, 0.f);
        #pragma unroll
        for (int p = 0; p < CLUSTER_SZ; p++) {
            const float2 v = pp[p * 256 + t];
            s.x += v.x; s.y += v.y;
        }
        reinterpret_cast<float2*>(Mc)[t] = s;
    }
    __syncthreads();

    // ================= Phase 3: quadform contribution ======================
    {
        float dots[8];
        #pragma unroll
        for (int r = 0; r < 8; r++) {
            const float4* __restrict__ m4 =
                reinterpret_cast<const float4*>(Mc + r * R_RANK) + half * 8;
            float dd = 0.f;
            #pragma unroll
            for (int j = 0; j < 8; j++) {
                const float4 mv = m4[j];
                dd += f[j].x * mv.x + f[j].y * mv.y
                    + f[j].z * mv.z + f[j].w * mv.w;
            }
            dots[r] = dd;
        }
        float s = f8a.x * dots[0] + f8a.y * dots[1]
                + f8a.z * dots[2] + f8a.w * dots[3]
                + f8b.x * dots[4] + f8b.y * dots[5]
                + f8b.z * dots[6] + f8b.w * dots[7];
        s += __shfl_xor_sync(0xffffffffu, s, 1);   // combine r2 halves
        if (half == 0)
            atomicAdd(&out[k], s * (1.0f / (float)D_DIRS));
    }
}

extern "C" void kernel_launch(void* const* d_in, const int* in_sizes, int n_in,
                              void* d_out, int out_size)
{
    const float* atten = (const float*)d_in[0];   // [D,P,R] fp32
    const float* rad   = (const float*)d_in[1];   // [D,P,R] fp32
    const float* F     = (const float*)d_in[2];   // [K,R]   fp32
    float* out = (float*)d_out;                   // [K]     fp32

    (void)in_sizes; (void)n_in; (void)out_size;

    reduce_p_kernel<<<2 * D_DIRS + PREFETCH_BLOCKS, 256>>>(atten, rad, F, out);

    // PDL + cluster launch for the single tail kernel
    cudaLaunchAttribute attrs[2];
    attrs[0].id = cudaLaunchAttributeProgrammaticStreamSerialization;
    attrs[0].val.programmaticStreamSerializationAllowed = 1;
    attrs[1].id = cudaLaunchAttributeClusterDimension;
    attrs[1].val.clusterDim.x = CLUSTER_SZ;
    attrs[1].val.clusterDim.y = 1;
    attrs[1].val.clusterDim.z = 1;

    cudaLaunchConfig_t cfg = {};
    cfg.gridDim  = dim3(TAIL_BLOCKS, 1, 1);
    cfg.blockDim = dim3(256, 1, 1);
    cfg.attrs = attrs;
    cfg.numAttrs = 2;
    cfg.stream = 0;

    cudaLaunchKernelEx(&cfg, tail_kernel, F, out);
}

// round 16
// speedup vs baseline: 1.4543x; 1.0295x over previous
#include <cuda_runtime.h>
#include <cstdint>

// Problem shape (fixed by dataset): D=1024, P=256, R=64, K=1024
#define D_DIRS 1024
#define P_PTS  256
#define R_RANK 64
#define K_SUB  1024

#define PREFETCH_BLOCKS 16

#define CLUSTER_SZ 8            // blocks per cluster
#define NCLUSTER   8            // clusters; each owns 8 r1 rows
#define TAIL_BLOCKS (CLUSTER_SZ * NCLUSTER)   // 64

// Scratch (allocation-free rule: __device__ globals)
__device__ float g_asum[D_DIRS * R_RANK];
__device__ float g_bsum[D_DIRS * R_RANK];
__device__ float g_sink[PREFETCH_BLOCKS];

// ---------------------------------------------------------------------------
// Kernel 1: reduce over P. LDG streaming (fastest measured variant: ~23.8us
// @ 72% DRAM). One block per (tensor, d); batched float4 __ldcs loads.
// 16 extra blocks prefetch F into L2; prefetch block 0 zeroes `out` for the
// tail's depth-8 atomics (ordered by the PDL grid dependency).
// ---------------------------------------------------------------------------
__global__ __launch_bounds__(256) void reduce_p_kernel(
    const float* __restrict__ atten, const float* __restrict__ rad,
    const float* __restrict__ F, float* __restrict__ out)
{
    const int b = blockIdx.x;
    const int t = threadIdx.x;

    if (b >= 2 * D_DIRS) {
        const int pb = b - 2 * D_DIRS;
        if (pb == 0)
            reinterpret_cast<float4*>(out)[t] = make_float4(0.f, 0.f, 0.f, 0.f);
        const float4* __restrict__ f4 =
            reinterpret_cast<const float4*>(F) + (size_t)pb * 1024;
        float4 acc = make_float4(0.f, 0.f, 0.f, 0.f);
        #pragma unroll
        for (int i = 0; i < 4; i++) {
            float4 v = f4[i * 256 + t];   // default caching -> lands in L2
            acc.x += v.x; acc.y += v.y; acc.z += v.z; acc.w += v.w;
        }
        if (t == 0) g_sink[pb] = acc.x + acc.y + acc.z + acc.w;
        cudaTriggerProgrammaticLaunchCompletion();
        return;
    }

    const bool is_b = (b >= D_DIRS);
    const int d = b & (D_DIRS - 1);
    const float* __restrict__ src = is_b ? rad : atten;
    float* __restrict__ dst = is_b ? g_bsum : g_asum;

    const float4* __restrict__ in =
        reinterpret_cast<const float4*>(src) + (size_t)d * (P_PTS * R_RANK / 4);

    float4 acc = make_float4(0.f, 0.f, 0.f, 0.f);
    #pragma unroll
    for (int i = 0; i < 16; i++) {
        float4 v = __ldcs(&in[i * 256 + t]);
        acc.x += v.x; acc.y += v.y; acc.z += v.z; acc.w += v.w;
    }

    __shared__ float4 s[256];
    s[t] = acc;
    __syncthreads();

    if (t < 16) {
        float4 sum = s[t];
        #pragma unroll
        for (int j = 1; j < 16; j++) {
            float4 v = s[j * 16 + t];
            sum.x += v.x; sum.y += v.y; sum.z += v.z; sum.w += v.w;
        }
        reinterpret_cast<float4*>(dst + d * R_RANK)[t] = sum;
    }
    cudaTriggerProgrammaticLaunchCompletion();
}

// ---------------- DSMEM helpers ----------------
__device__ __forceinline__ uint32_t smem_u32(const void* p)
{
    uint32_t a;
    asm("{ .reg .u64 tmp; cvta.to.shared.u64 tmp, %1; cvt.u32.u64 %0, tmp; }"
        : "=r"(a) : "l"(p));
    return a;
}
__device__ __forceinline__ float2 dsmem_ld_f2(uint32_t local_addr, uint32_t rank)
{
    uint32_t remote;
    asm volatile("mapa.shared::cluster.u32 %0, %1, %2;"
                 : "=r"(remote) : "r"(local_addr), "r"(rank));
    float2 v;
    asm volatile("ld.shared::cluster.v2.f32 {%0, %1}, [%2];"
                 : "=f"(v.x), "=f"(v.y) : "r"(remote));
    return v;
}

// ---------------------------------------------------------------------------
// Kernel 2 (single PDL tail, cluster-synced, DSMEM combine):
// 64 blocks = 8 clusters x 8. Cluster cid owns M rows r1 in [8cid, 8cid+8);
// block cr computes those rows over d-chunk [128cr, +128) into OWN smem
// (thread pairs split the d range: 64 serial iters), cluster.sync, then each
// block sums all 8 peers' partials via DSMEM -> final M rows in smem ->
// quadform contribution for k-slice [128cr, +128), spread atomicAdd depth 8.
// ---------------------------------------------------------------------------
__global__ __launch_bounds__(256) void tail_kernel(
    const float* __restrict__ F, float* __restrict__ out)
{
    __shared__ __align__(16) float sB[128 * R_RANK];   // 32 KB  bsum chunk
    __shared__ __align__(16) float sAc[128 * 8];       // 4 KB   asum columns
    __shared__ __align__(16) float Mpart[8 * R_RANK];  // 2 KB   own partial (peers read)
    __shared__ __align__(16) float Mc[8 * R_RANK];     // 2 KB   combined M rows

    const int t   = threadIdx.x;
    const int cid = blockIdx.x / CLUSTER_SZ;   // r1 range owner
    const int cr  = blockIdx.x % CLUSTER_SZ;   // d chunk & k slice

    // ---- prestage F in registers (independent of predecessors) ----
    const int kl = t >> 1, half = t & 1;
    const int k  = cr * 128 + kl;
    const float4* __restrict__ fr =
        reinterpret_cast<const float4*>(F) + (size_t)k * 16;
    float4 f[8];
    #pragma unroll
    for (int j = 0; j < 8; j++) f[j] = fr[half * 8 + j];
    const float4 f8a = fr[2 * cid];        // f_k[8cid .. 8cid+3]
    const float4 f8b = fr[2 * cid + 1];    // f_k[8cid+4 .. 8cid+7]

    cudaGridDependencySynchronize();       // stream complete (incl. out = 0)

    // ================= Phase 1: partial M rows over 128 d's ================
    const int dbase = cr * 128;
    {
        const float4* __restrict__ b4 =
            reinterpret_cast<const float4*>(g_bsum) + (size_t)dbase * 16;
        #pragma unroll
        for (int i = 0; i < 8; i++)
            reinterpret_cast<float4*>(sB)[i * 256 + t] = b4[i * 256 + t];
        #pragma unroll
        for (int i = 0; i < 4; i++) {
            const int idx = i * 256 + t;
            const int dl = idx >> 3, rr = idx & 7;
            sAc[idx] = g_asum[(size_t)(dbase + dl) * R_RANK + 8 * cid + rr];
        }
    }
    __syncthreads();

    {
        const int w = t >> 5;        // warp = local r1 row (0..7)
        const int l = t & 31;
        const int q = l & 15;        // float4 column (r2 = 4q)
        const int h = l >> 4;        // d-half (0: d<64, 1: d>=64)

        float4 acc = make_float4(0.f, 0.f, 0.f, 0.f);
        #pragma unroll 8
        for (int i = 0; i < 64; i++) {
            const int d = h * 64 + i;
            const float a = sAc[d * 8 + w];
            const float4 bv =
                reinterpret_cast<const float4*>(sB + d * R_RANK)[q];
            acc.x += a * bv.x; acc.y += a * bv.y;
            acc.z += a * bv.z; acc.w += a * bv.w;
        }
        // combine d-halves across the warp (lanes l and l^16)
        acc.x += __shfl_xor_sync(0xffffffffu, acc.x, 16);
        acc.y += __shfl_xor_sync(0xffffffffu, acc.y, 16);
        acc.z += __shfl_xor_sync(0xffffffffu, acc.z, 16);
        acc.w += __shfl_xor_sync(0xffffffffu, acc.w, 16);
        if (h == 0)
            reinterpret_cast<float4*>(Mpart + w * R_RANK)[q] = acc;
    }

    // cluster-wide: all Mpart writes visible to peer CTAs
    asm volatile("barrier.cluster.arrive.aligned;" ::: "memory");
    asm volatile("barrier.cluster.wait.aligned;" ::: "memory");

    // ================= Phase 2: DSMEM combine -> Mc =========================
    {
        const uint32_t mp = smem_u32(Mpart) + t * 8;   // this thread's float2
        float2 s = make_float2(0.f, 0.f);
        #pragma unroll
        for (int p = 0; p < CLUSTER_SZ; p++) {
            const float2 v = dsmem_ld_f2(mp, (uint32_t)p);
            s.x += v.x; s.y += v.y;
        }
        reinterpret_cast<float2*>(Mc)[t] = s;
    }
    __syncthreads();

    // done reading peers' smem -> arrive; wait before exit (after phase 3)
    asm volatile("barrier.cluster.arrive.aligned;" ::: "memory");

    // ================= Phase 3: quadform contribution ======================
    {
        float dots[8];
        #pragma unroll
        for (int r = 0; r < 8; r++) {
            const float4* __restrict__ m4 =
                reinterpret_cast<const float4*>(Mc + r * R_RANK) + half * 8;
            float dd = 0.f;
            #pragma unroll
            for (int j = 0; j < 8; j++) {
                const float4 mv = m4[j];
                dd += f[j].x * mv.x + f[j].y * mv.y
                    + f[j].z * mv.z + f[j].w * mv.w;
            }
            dots[r] = dd;
        }
        float s = f8a.x * dots[0] + f8a.y * dots[1]
                + f8a.z * dots[2] + f8a.w * dots[3]
                + f8b.x * dots[4] + f8b.y * dots[5]
                + f8b.z * dots[6] + f8b.w * dots[7];
        s += __shfl_xor_sync(0xffffffffu, s, 1);   // combine r2 halves
        if (half == 0)
            atomicAdd(&out[k], s * (1.0f / (float)D_DIRS));
    }

    // no CTA exits while a peer might still be reading its smem
    asm volatile("barrier.cluster.wait.aligned;" ::: "memory");
}

extern "C" void kernel_launch(void* const* d_in, const int* in_sizes, int n_in,
                              void* d_out, int out_size)
{
    const float* atten = (const float*)d_in[0];   // [D,P,R] fp32
    const float* rad   = (const float*)d_in[1];   // [D,P,R] fp32
    const float* F     = (const float*)d_in[2];   // [K,R]   fp32
    float* out = (float*)d_out;                   // [K]     fp32

    (void)in_sizes; (void)n_in; (void)out_size;

    reduce_p_kernel<<<2 * D_DIRS + PREFETCH_BLOCKS, 256>>>(atten, rad, F, out);

    // PDL + cluster launch for the single tail kernel
    cudaLaunchAttribute attrs[2];
    attrs[0].id = cudaLaunchAttributeProgrammaticStreamSerialization;
    attrs[0].val.programmaticStreamSerializationAllowed = 1;
    attrs[1].id = cudaLaunchAttributeClusterDimension;
    attrs[1].val.clusterDim.x = CLUSTER_SZ;
    attrs[1].val.clusterDim.y = 1;
    attrs[1].val.clusterDim.z = 1;

    cudaLaunchConfig_t cfg = {};
    cfg.gridDim  = dim3(TAIL_BLOCKS, 1, 1);
    cfg.blockDim = dim3(256, 1, 1);
    cfg.attrs = attrs;
    cfg.numAttrs = 2;
    cfg.stream = 0;

    cudaLaunchKernelEx(&cfg, tail_kernel, F, out);
}

// round 17
// speedup vs baseline: 1.4557x; 1.0010x over previous
#include <cuda_runtime.h>
#include <cstdint>

// Problem shape (fixed by dataset): D=1024, P=256, R=64, K=1024
#define D_DIRS 1024
#define P_PTS  256
#define R_RANK 64
#define K_SUB  1024

#define PREFETCH_BLOCKS 16

#define CLUSTER_SZ 8            // blocks per cluster
#define NCLUSTER   8            // clusters; each owns 8 r1 rows
#define TAIL_BLOCKS (CLUSTER_SZ * NCLUSTER)   // 64

// Scratch (allocation-free rule: __device__ globals)
__device__ float g_asum[D_DIRS * R_RANK];
__device__ float g_bsum[D_DIRS * R_RANK];
__device__ float g_sink[PREFETCH_BLOCKS];

// ---------------------------------------------------------------------------
// Kernel 1: reduce over P, dual-slab. ONE block per direction d streams BOTH
// atten[d] and rad[d] (128 KB). Grid = 1024+16 = 1040 blocks at 8 blocks/SM
// (1216 slots) -> exactly ONE wave: no wave-quantization drain.
// __launch_bounds__(256, 8) pins regs <= 32 so 8 blocks/SM holds.
// 16 extra blocks prefetch F into L2; prefetch block 0 zeroes `out`.
// ---------------------------------------------------------------------------
__global__ __launch_bounds__(256, 8) void reduce_p_kernel(
    const float* __restrict__ atten, const float* __restrict__ rad,
    const float* __restrict__ F, float* __restrict__ out)
{
    const int b = blockIdx.x;
    const int t = threadIdx.x;

    if (b >= D_DIRS) {
        const int pb = b - D_DIRS;
        if (pb == 0)
            reinterpret_cast<float4*>(out)[t] = make_float4(0.f, 0.f, 0.f, 0.f);
        const float4* __restrict__ f4 =
            reinterpret_cast<const float4*>(F) + (size_t)pb * 1024;
        float4 acc = make_float4(0.f, 0.f, 0.f, 0.f);
        #pragma unroll
        for (int i = 0; i < 4; i++) {
            float4 v = f4[i * 256 + t];   // default caching -> lands in L2
            acc.x += v.x; acc.y += v.y; acc.z += v.z; acc.w += v.w;
        }
        if (t == 0) g_sink[pb] = acc.x + acc.y + acc.z + acc.w;
        cudaTriggerProgrammaticLaunchCompletion();
        return;
    }

    const int d = b;
    const float4* __restrict__ inA =
        reinterpret_cast<const float4*>(atten) + (size_t)d * 4096;
    const float4* __restrict__ inB =
        reinterpret_cast<const float4*>(rad) + (size_t)d * 4096;

    float4 accA = make_float4(0.f, 0.f, 0.f, 0.f);
    float4 accB = make_float4(0.f, 0.f, 0.f, 0.f);
    #pragma unroll
    for (int i = 0; i < 16; i++) {
        float4 va = __ldcs(&inA[i * 256 + t]);
        float4 vb = __ldcs(&inB[i * 256 + t]);
        accA.x += va.x; accA.y += va.y; accA.z += va.z; accA.w += va.w;
        accB.x += vb.x; accB.y += vb.y; accB.z += vb.z; accB.w += vb.w;
    }

    __shared__ float4 s[256];

    // ---- reduce A ----
    s[t] = accA;
    __syncthreads();
    if (t < 16) {
        float4 sum = s[t];
        #pragma unroll
        for (int j = 1; j < 16; j++) {
            float4 v = s[j * 16 + t];
            sum.x += v.x; sum.y += v.y; sum.z += v.z; sum.w += v.w;
        }
        reinterpret_cast<float4*>(g_asum + d * R_RANK)[t] = sum;
    }
    __syncthreads();

    // ---- reduce B ----
    s[t] = accB;
    __syncthreads();
    if (t < 16) {
        float4 sum = s[t];
        #pragma unroll
        for (int j = 1; j < 16; j++) {
            float4 v = s[j * 16 + t];
            sum.x += v.x; sum.y += v.y; sum.z += v.z; sum.w += v.w;
        }
        reinterpret_cast<float4*>(g_bsum + d * R_RANK)[t] = sum;
    }
    cudaTriggerProgrammaticLaunchCompletion();
}

// ---------------- DSMEM helpers ----------------
__device__ __forceinline__ uint32_t smem_u32(const void* p)
{
    uint32_t a;
    asm("{ .reg .u64 tmp; cvta.to.shared.u64 tmp, %1; cvt.u32.u64 %0, tmp; }"
        : "=r"(a) : "l"(p));
    return a;
}
__device__ __forceinline__ float2 dsmem_ld_f2(uint32_t local_addr, uint32_t rank)
{
    uint32_t remote;
    asm volatile("mapa.shared::cluster.u32 %0, %1, %2;"
                 : "=r"(remote) : "r"(local_addr), "r"(rank));
    float2 v;
    asm volatile("ld.shared::cluster.v2.f32 {%0, %1}, [%2];"
                 : "=f"(v.x), "=f"(v.y) : "r"(remote));
    return v;
}

// ---------------------------------------------------------------------------
// Kernel 2 (single PDL tail, cluster-synced, DSMEM combine) — unchanged from
// the proven round-16 version. 64 blocks = 8 clusters x 8; cluster cid owns
// M rows [8cid, 8cid+8); block cr covers d-chunk [128cr, +128) and k-slice
// [128cr, +128); spread atomicAdd into out at depth 8.
// ---------------------------------------------------------------------------
__global__ __launch_bounds__(256) void tail_kernel(
    const float* __restrict__ F, float* __restrict__ out)
{
    __shared__ __align__(16) float sB[128 * R_RANK];   // 32 KB
    __shared__ __align__(16) float sAc[128 * 8];       // 4 KB
    __shared__ __align__(16) float Mpart[8 * R_RANK];  // 2 KB (peers read)
    __shared__ __align__(16) float Mc[8 * R_RANK];     // 2 KB

    const int t   = threadIdx.x;
    const int cid = blockIdx.x / CLUSTER_SZ;
    const int cr  = blockIdx.x % CLUSTER_SZ;

    // prestage F in registers (independent of predecessors)
    const int kl = t >> 1, half = t & 1;
    const int k  = cr * 128 + kl;
    const float4* __restrict__ fr =
        reinterpret_cast<const float4*>(F) + (size_t)k * 16;
    float4 f[8];
    #pragma unroll
    for (int j = 0; j < 8; j++) f[j] = fr[half * 8 + j];
    const float4 f8a = fr[2 * cid];
    const float4 f8b = fr[2 * cid + 1];

    cudaGridDependencySynchronize();   // stream complete (incl. out = 0)

    // ---- Phase 1: partial M rows over 128 d's ----
    const int dbase = cr * 128;
    {
        const float4* __restrict__ b4 =
            reinterpret_cast<const float4*>(g_bsum) + (size_t)dbase * 16;
        #pragma unroll
        for (int i = 0; i < 8; i++)
            reinterpret_cast<float4*>(sB)[i * 256 + t] = b4[i * 256 + t];
        #pragma unroll
        for (int i = 0; i < 4; i++) {
            const int idx = i * 256 + t;
            const int dl = idx >> 3, rr = idx & 7;
            sAc[idx] = g_asum[(size_t)(dbase + dl) * R_RANK + 8 * cid + rr];
        }
    }
    __syncthreads();

    {
        const int w = t >> 5;        // local r1 row
        const int l = t & 31;
        const int q = l & 15;        // float4 column
        const int h = l >> 4;        // d-half

        float4 acc = make_float4(0.f, 0.f, 0.f, 0.f);
        #pragma unroll 8
        for (int i = 0; i < 64; i++) {
            const int d = h * 64 + i;
            const float a = sAc[d * 8 + w];
            const float4 bv =
                reinterpret_cast<const float4*>(sB + d * R_RANK)[q];
            acc.x += a * bv.x; acc.y += a * bv.y;
            acc.z += a * bv.z; acc.w += a * bv.w;
        }
        acc.x += __shfl_xor_sync(0xffffffffu, acc.x, 16);
        acc.y += __shfl_xor_sync(0xffffffffu, acc.y, 16);
        acc.z += __shfl_xor_sync(0xffffffffu, acc.z, 16);
        acc.w += __shfl_xor_sync(0xffffffffu, acc.w, 16);
        if (h == 0)
            reinterpret_cast<float4*>(Mpart + w * R_RANK)[q] = acc;
    }

    asm volatile("barrier.cluster.arrive.aligned;" ::: "memory");
    asm volatile("barrier.cluster.wait.aligned;" ::: "memory");

    // ---- Phase 2: DSMEM combine -> Mc ----
    {
        const uint32_t mp = smem_u32(Mpart) + t * 8;
        float2 s = make_float2(0.f, 0.f);
        #pragma unroll
        for (int p = 0; p < CLUSTER_SZ; p++) {
            const float2 v = dsmem_ld_f2(mp, (uint32_t)p);
            s.x += v.x; s.y += v.y;
        }
        reinterpret_cast<float2*>(Mc)[t] = s;
    }
    __syncthreads();

    asm volatile("barrier.cluster.arrive.aligned;" ::: "memory");

    // ---- Phase 3: quadform contribution ----
    {
        float dots[8];
        #pragma unroll
        for (int r = 0; r < 8; r++) {
            const float4* __restrict__ m4 =
                reinterpret_cast<const float4*>(Mc + r * R_RANK) + half * 8;
            float dd = 0.f;
            #pragma unroll
            for (int j = 0; j < 8; j++) {
                const float4 mv = m4[j];
                dd += f[j].x * mv.x + f[j].y * mv.y
                    + f[j].z * mv.z + f[j].w * mv.w;
            }
            dots[r] = dd;
        }
        float s = f8a.x * dots[0] + f8a.y * dots[1]
                + f8a.z * dots[2] + f8a.w * dots[3]
                + f8b.x * dots[4] + f8b.y * dots[5]
                + f8b.z * dots[6] + f8b.w * dots[7];
        s += __shfl_xor_sync(0xffffffffu, s, 1);
        if (half == 0)
            atomicAdd(&out[k], s * (1.0f / (float)D_DIRS));
    }

    asm volatile("barrier.cluster.wait.aligned;" ::: "memory");
}

extern "C" void kernel_launch(void* const* d_in, const int* in_sizes, int n_in,
                              void* d_out, int out_size)
{
    const float* atten = (const float*)d_in[0];   // [D,P,R] fp32
    const float* rad   = (const float*)d_in[1];   // [D,P,R] fp32
    const float* F     = (const float*)d_in[2];   // [K,R]   fp32
    float* out = (float*)d_out;                   // [K]     fp32

    (void)in_sizes; (void)n_in; (void)out_size;

    reduce_p_kernel<<<D_DIRS + PREFETCH_BLOCKS, 256>>>(atten, rad, F, out);

    cudaLaunchAttribute attrs[2];
    attrs[0].id = cudaLaunchAttributeProgrammaticStreamSerialization;
    attrs[0].val.programmaticStreamSerializationAllowed = 1;
    attrs[1].id = cudaLaunchAttributeClusterDimension;
    attrs[1].val.clusterDim.x = CLUSTER_SZ;
    attrs[1].val.clusterDim.y = 1;
    attrs[1].val.clusterDim.z = 1;

    cudaLaunchConfig_t cfg = {};
    cfg.gridDim  = dim3(TAIL_BLOCKS, 1, 1);
    cfg.blockDim = dim3(256, 1, 1);
    cfg.attrs = attrs;
    cfg.numAttrs = 2;
    cfg.stream = 0;

    cudaLaunchKernelEx(&cfg, tail_kernel, F, out);
}